// round 5
// baseline (speedup 1.0000x reference)
#include <cuda_runtime.h>

// Problem constants (fixed by reference setup_inputs)
#define N_NODES 100000
#define E_EDGES 1600000
#define F0 128
#define F1 64
#define F2 40

// ---------------- static scratch (no allocations allowed) ----------------
__device__ int   g_is64;                // edge_index dtype flag (device-detected)
__device__ float g_deg[N_NODES];
__device__ float g_dinv[N_NODES];
__device__ int   g_src[E_EDGES];
__device__ int   g_dst[E_EDGES];
__device__ int   g_cnt[N_NODES];        // per-dst edge count
__device__ int   g_rs_part[N_NODES];    // block-local exclusive scan
__device__ int   g_bsum[128];           // per-block totals
__device__ int   g_row_start[N_NODES + 1];
__device__ int   g_cursor[N_NODES];
__device__ int2  g_csr[E_EDGES];        // packed {src, norm_bits}, grouped by dst
__device__ float g_h1[(size_t)N_NODES * F1];    // x @ W1
__device__ float g_agg1[(size_t)N_NODES * F1];  // aggregated + bias + relu
__device__ float g_h2[(size_t)N_NODES * F2];    // agg1 @ W2

// ---------------- dtype sniff: int64 edge_index has all-zero odd 32-bit words ----------------
__global__ void k_detect(const int* __restrict__ ei32) {
    if (blockIdx.x == 0 && threadIdx.x == 0) {
        int any = 0;
        for (int i = 0; i < 1024; i++) any |= ei32[2 * i + 1];
        g_is64 = (any == 0) ? 1 : 0;
    }
}

// ---------------- init: deg=1 (self loop), cnt=0 ----------------
__global__ void k_init(int n) {
    int i = blockIdx.x * blockDim.x + threadIdx.x;
    if (i < n) { g_deg[i] = 1.0f; g_cnt[i] = 0; }
}

// ---------------- edge pass: decode (either dtype), degree + count ----------------
__global__ void k_edge_prep(const int* __restrict__ ei32,
                            const float* __restrict__ w, int E, int n) {
    int e = blockIdx.x * blockDim.x + threadIdx.x;
    if (e >= E) return;
    int s, d;
    if (g_is64) {                                  // int64, little-endian low words
        s = ei32[2 * (size_t)e];
        d = ei32[2 * ((size_t)E + e)];
    } else {                                       // int32
        s = ei32[e];
        d = ei32[(size_t)E + e];
    }
    if ((unsigned)s >= (unsigned)n) s = 0;         // safety clamp
    if ((unsigned)d >= (unsigned)n) d = 0;
    g_src[e] = s;
    g_dst[e] = d;
    atomicAdd(&g_deg[d], w[e]);
    atomicAdd(&g_cnt[d], 1);
}

__global__ void k_dinv(int n) {
    int i = blockIdx.x * blockDim.x + threadIdx.x;
    if (i >= n) return;
    float dg = g_deg[i];
    g_dinv[i] = (dg > 0.f) ? rsqrtf(dg) : 0.f;
}

// ---------------- exclusive scan of g_cnt (3 kernels) ----------------
__global__ void k_scan1(int n) {
    __shared__ int sh[1024];
    int i = blockIdx.x * 1024 + threadIdx.x;
    int v = (i < n) ? g_cnt[i] : 0;
    sh[threadIdx.x] = v;
    __syncthreads();
    for (int off = 1; off < 1024; off <<= 1) {
        int t = 0;
        if (threadIdx.x >= off) t = sh[threadIdx.x - off];
        __syncthreads();
        sh[threadIdx.x] += t;
        __syncthreads();
    }
    int incl = sh[threadIdx.x];
    if (i < n) g_rs_part[i] = incl - v;   // exclusive within block
    if (threadIdx.x == 1023) g_bsum[blockIdx.x] = incl;
}

__global__ void k_scan2(int nb) {
    if (threadIdx.x == 0 && blockIdx.x == 0) {
        int run = 0;
        for (int b = 0; b < nb; b++) { int t = g_bsum[b]; g_bsum[b] = run; run += t; }
    }
}

__global__ void k_scan3(int n, int E) {
    int i = blockIdx.x * blockDim.x + threadIdx.x;
    if (i < n) {
        int rs = g_rs_part[i] + g_bsum[i >> 10];
        g_row_start[i] = rs;
        g_cursor[i] = rs;
    }
    if (i == 0) g_row_start[n] = E;
}

// ---------------- fill CSR: grouped-by-dst packed (src, norm) ----------------
__global__ void k_fill(const float* __restrict__ w, int E) {
    int e = blockIdx.x * blockDim.x + threadIdx.x;
    if (e >= E) return;
    int s = g_src[e];
    int d = g_dst[e];
    float nv = g_dinv[s] * w[e] * g_dinv[d];
    int pos = atomicAdd(&g_cursor[d], 1);
    if (pos >= 0 && pos < E) g_csr[pos] = make_int2(s, __float_as_int(nv));
}

// ---------------- register-blocked fp32 GEMM: C[nrows,NC] = A[nrows,KDIM] @ W[KDIM,NC]
// blockDim.x = RPB * (NC/8). Each thread computes 1 row x 8 cols.
template <int KDIM, int NC, int RPB>
__global__ void k_gemm(const float* __restrict__ A, const float* __restrict__ W,
                       float* __restrict__ C, int nrows) {
    constexpr int TC = NC / 8;
    constexpr int APAD = KDIM + 4;   // bank-shift padding
    __shared__ float Ws[KDIM * NC];
    __shared__ float As[RPB * APAD];

    int tid = threadIdx.x;
    int nthr = blockDim.x;

    for (int i = tid; i < KDIM * NC / 4; i += nthr)
        ((float4*)Ws)[i] = ((const float4*)W)[i];

    int row0 = blockIdx.x * RPB;
    for (int i = tid; i < RPB * (KDIM / 4); i += nthr) {
        int r = i / (KDIM / 4);
        int kc = i % (KDIM / 4);
        int grow = row0 + r;
        float4 v = make_float4(0.f, 0.f, 0.f, 0.f);
        if (grow < nrows) v = ((const float4*)(A + (size_t)grow * KDIM))[kc];
        *(float4*)&As[r * APAD + kc * 4] = v;
    }
    __syncthreads();

    int r  = tid / TC;
    int c0 = (tid % TC) * 8;
    float acc[8];
#pragma unroll
    for (int j = 0; j < 8; j++) acc[j] = 0.f;

#pragma unroll 8
    for (int k = 0; k < KDIM; k++) {
        float a = As[r * APAD + k];
        float4 w0 = *(const float4*)&Ws[k * NC + c0];
        float4 w1 = *(const float4*)&Ws[k * NC + c0 + 4];
        acc[0] = fmaf(a, w0.x, acc[0]);
        acc[1] = fmaf(a, w0.y, acc[1]);
        acc[2] = fmaf(a, w0.z, acc[2]);
        acc[3] = fmaf(a, w0.w, acc[3]);
        acc[4] = fmaf(a, w1.x, acc[4]);
        acc[5] = fmaf(a, w1.y, acc[5]);
        acc[6] = fmaf(a, w1.z, acc[6]);
        acc[7] = fmaf(a, w1.w, acc[7]);
    }

    int grow = row0 + r;
    if (grow < nrows) {
        float4* op = (float4*)(C + (size_t)grow * NC + c0);
        op[0] = make_float4(acc[0], acc[1], acc[2], acc[3]);
        op[1] = make_float4(acc[4], acc[5], acc[6], acc[7]);
    }
}

// ---------------- CSR gather: out[row] = sum_{e in row} h[src_e]*norm_e
//                              + h[row]*dinv^2 + bias (+ optional relu)
// thread = (node, float4-column). NC4 = NC/4.
template <int NC4, bool RELU>
__global__ void k_gather(const float* __restrict__ h, const float* __restrict__ bias,
                         float* __restrict__ out, int n) {
    int tid = blockIdx.x * blockDim.x + threadIdx.x;
    if (tid >= n * NC4) return;
    int row = tid / NC4;
    int c   = tid % NC4;

    const float4* h4 = (const float4*)h;
    float di = g_dinv[row];
    float s2 = di * di;

    // self loop
    float4 self = h4[(size_t)row * NC4 + c];
    float4 acc = make_float4(self.x * s2, self.y * s2, self.z * s2, self.w * s2);

    int beg = g_row_start[row];
    int end = g_row_start[row + 1];
    for (int j = beg; j < end; j++) {
        int2 p = g_csr[j];                 // broadcast across the node's lanes
        float nv = __int_as_float(p.y);
        float4 v = h4[(size_t)p.x * NC4 + c];
        acc.x = fmaf(v.x, nv, acc.x);
        acc.y = fmaf(v.y, nv, acc.y);
        acc.z = fmaf(v.z, nv, acc.z);
        acc.w = fmaf(v.w, nv, acc.w);
    }

    float4 b = ((const float4*)bias)[c];
    acc.x += b.x; acc.y += b.y; acc.z += b.z; acc.w += b.w;
    if (RELU) {
        acc.x = fmaxf(acc.x, 0.f); acc.y = fmaxf(acc.y, 0.f);
        acc.z = fmaxf(acc.z, 0.f); acc.w = fmaxf(acc.w, 0.f);
    }
    ((float4*)out)[(size_t)row * NC4 + c] = acc;
}

// ---------------- finalize: log_softmax in place, one warp per row ----------------
__global__ void k_finalize(float* __restrict__ out, int n) {
    int row = blockIdx.x * blockDim.y + threadIdx.y;
    if (row >= n) return;
    int lane = threadIdx.x;
    float* orow = out + (size_t)row * F2;

    float v0 = orow[lane];
    float v1 = 0.f;
    bool has2 = (lane < F2 - 32);
    if (has2) v1 = orow[lane + 32];

    float m = v0;
    if (has2) m = fmaxf(m, v1);
#pragma unroll
    for (int off = 16; off > 0; off >>= 1)
        m = fmaxf(m, __shfl_xor_sync(0xffffffffu, m, off));

    float s = expf(v0 - m);
    if (has2) s += expf(v1 - m);
#pragma unroll
    for (int off = 16; off > 0; off >>= 1)
        s += __shfl_xor_sync(0xffffffffu, s, off);

    float lse = m + logf(s);
    orow[lane] = v0 - lse;
    if (has2) orow[lane + 32] = v1 - lse;
}

// ---------------- host launcher ----------------
extern "C" void kernel_launch(void* const* d_in, const int* in_sizes, int n_in,
                              void* d_out, int out_size) {
    // Identify inputs by element count (all 7 are distinct), robust to any
    // metadata ordering:
    //   x=N*128 (largest), edge_index=2E, edge_weight=E,
    //   W1=128*64, W2=64*40, b1=64, b2=40
    int order[16];
    for (int i = 0; i < n_in; i++) order[i] = i;
    for (int a = 0; a < n_in; a++)           // selection sort by size, descending
        for (int bidx = a + 1; bidx < n_in; bidx++)
            if (in_sizes[order[bidx]] > in_sizes[order[a]]) {
                int t = order[a]; order[a] = order[bidx]; order[bidx] = t;
            }

    const float* x   = (const float*)d_in[order[0]];
    const int*   ei  = (const int*)  d_in[order[1]];   // int32 view; dtype sniffed on device
    const float* w   = (const float*)d_in[order[2]];
    const float* W1  = (const float*)d_in[order[3]];
    const float* W2  = (const float*)d_in[order[4]];
    const float* b1  = (const float*)d_in[order[5]];
    const float* b2  = (const float*)d_in[order[6]];
    float* out = (float*)d_out;

    int N = in_sizes[order[0]] / F0;   // 100000
    int E = in_sizes[order[2]];        // 1600000
    if (N > N_NODES) N = N_NODES;
    if (E > E_EDGES) E = E_EDGES;

    const int T = 256;
    int NB = (N + 1023) / 1024;

    // ---- dtype sniff + normalization + CSR build ----
    k_detect<<<1, 32>>>(ei);
    k_init<<<(N + T - 1) / T, T>>>(N);
    k_edge_prep<<<(E + T - 1) / T, T>>>(ei, w, E, N);
    k_dinv<<<(N + T - 1) / T, T>>>(N);
    k_scan1<<<NB, 1024>>>(N);
    k_scan2<<<1, 32>>>(NB);
    k_scan3<<<(N + T - 1) / T, T>>>(N, E);
    k_fill<<<(E + T - 1) / T, T>>>(w, E);

    // ---- layer 1 ----
    k_gemm<F0, F1, 16><<<(N + 15) / 16, 16 * (F1 / 8)>>>(x, W1, g_h1, N);
    k_gather<F1 / 4, true><<<(N * (F1 / 4) + T - 1) / T, T>>>(g_h1, b1, g_agg1, N);

    // ---- layer 2 ----
    k_gemm<F1, F2, 32><<<(N + 31) / 32, 32 * (F2 / 8)>>>(g_agg1, W2, g_h2, N);
    k_gather<F2 / 4, false><<<(N * (F2 / 4) + T - 1) / T, T>>>(g_h2, b2, out, N);

    // ---- log_softmax ----
    k_finalize<<<(N + 3) / 4, dim3(32, 4)>>>(out, N);
}

// round 6
// speedup vs baseline: 1.2103x; 1.2103x over previous
#include <cuda_runtime.h>

// Problem constants (fixed by reference setup_inputs)
#define N_NODES 100000
#define E_EDGES 1600000
#define F0 128
#define F1 64
#define F2 40

// ---------------- static scratch (no allocations allowed) ----------------
__device__ int   g_is64;                // edge_index dtype flag (device-detected)
__device__ float g_deg[N_NODES];
__device__ float g_dinv[N_NODES];
__device__ int   g_src[E_EDGES];
__device__ int   g_dst[E_EDGES];
__device__ int   g_cnt[N_NODES];        // per-dst edge count
__device__ int   g_rs_part[N_NODES];    // block-local exclusive scan
__device__ int   g_bsum[128];           // per-block totals
__device__ int   g_row_start[N_NODES + 1];
__device__ int   g_cursor[N_NODES];
__device__ int2  g_csr[E_EDGES];        // packed {src, norm_bits}, grouped by dst
__device__ float g_h1[(size_t)N_NODES * F1];    // x @ W1
__device__ float g_agg1[(size_t)N_NODES * F1];  // aggregated + bias + relu
__device__ float g_h2[(size_t)N_NODES * F2];    // agg1 @ W2

// ---------------- init (deg=1, cnt=0) + parallel dtype sniff ----------------
// int64 edge_index (values < 2^31) has all-zero odd 32-bit words; int32 doesn't.
__global__ void k_init(const int* __restrict__ ei32, int n) {
    int i = blockIdx.x * blockDim.x + threadIdx.x;
    if (i < n) { g_deg[i] = 1.0f; g_cnt[i] = 0; }
    if (blockIdx.x == 0 && threadIdx.x < 32) {
        int lane = threadIdx.x;
        int any = 0;
#pragma unroll
        for (int k = 0; k < 32; k++)
            any |= ei32[2 * (lane + 32 * k) + 1];     // 32 lanes x 32 = 1024 samples
        unsigned b = __ballot_sync(0xffffffffu, any != 0);
        if (lane == 0) g_is64 = (b == 0u) ? 1 : 0;
    }
}

// ---------------- edge pass: decode (either dtype), degree + count ----------------
__global__ void k_edge_prep(const int* __restrict__ ei32,
                            const float* __restrict__ w, int E, int n) {
    int e = blockIdx.x * blockDim.x + threadIdx.x;
    if (e >= E) return;
    int s, d;
    if (g_is64) {                                  // int64, little-endian low words
        s = ei32[2 * (size_t)e];
        d = ei32[2 * ((size_t)E + e)];
    } else {                                       // int32
        s = ei32[e];
        d = ei32[(size_t)E + e];
    }
    if ((unsigned)s >= (unsigned)n) s = 0;         // safety clamp
    if ((unsigned)d >= (unsigned)n) d = 0;
    g_src[e] = s;
    g_dst[e] = d;
    atomicAdd(&g_deg[d], w[e]);
    atomicAdd(&g_cnt[d], 1);
}

// ---------------- scan phase 1 (block-local exclusive scan of cnt) + fused dinv ----------------
__global__ void k_scan1(int n) {
    __shared__ int sh[1024];
    int i = blockIdx.x * 1024 + threadIdx.x;

    // fused: dinv = rsqrt(deg)
    if (i < n) {
        float dg = g_deg[i];
        g_dinv[i] = (dg > 0.f) ? rsqrtf(dg) : 0.f;
    }

    int v = (i < n) ? g_cnt[i] : 0;
    sh[threadIdx.x] = v;
    __syncthreads();
    for (int off = 1; off < 1024; off <<= 1) {
        int t = 0;
        if (threadIdx.x >= off) t = sh[threadIdx.x - off];
        __syncthreads();
        sh[threadIdx.x] += t;
        __syncthreads();
    }
    int incl = sh[threadIdx.x];
    if (i < n) g_rs_part[i] = incl - v;   // exclusive within block
    if (threadIdx.x == 1023) g_bsum[blockIdx.x] = incl;
}

// ---------------- scan phase 2: parallel exclusive scan of <=128 block sums ----------------
__global__ void k_scan2(int nb) {
    __shared__ int sh[128];
    int t = threadIdx.x;
    int v = (t < nb) ? g_bsum[t] : 0;
    sh[t] = v;
    __syncthreads();
    for (int off = 1; off < 128; off <<= 1) {
        int u = 0;
        if (t >= off) u = sh[t - off];
        __syncthreads();
        sh[t] += u;
        __syncthreads();
    }
    if (t < nb) g_bsum[t] = sh[t] - v;    // exclusive
}

__global__ void k_scan3(int n, int E) {
    int i = blockIdx.x * blockDim.x + threadIdx.x;
    if (i < n) {
        int rs = g_rs_part[i] + g_bsum[i >> 10];
        g_row_start[i] = rs;
        g_cursor[i] = rs;
    }
    if (i == 0) g_row_start[n] = E;
}

// ---------------- fill CSR: grouped-by-dst packed (src, norm) ----------------
__global__ void k_fill(const float* __restrict__ w, int E) {
    int e = blockIdx.x * blockDim.x + threadIdx.x;
    if (e >= E) return;
    int s = g_src[e];
    int d = g_dst[e];
    float nv = g_dinv[s] * w[e] * g_dinv[d];
    int pos = atomicAdd(&g_cursor[d], 1);
    if (pos >= 0 && pos < E) g_csr[pos] = make_int2(s, __float_as_int(nv));
}

// ---------------- register-blocked fp32 GEMM: C[nrows,NC] = A[nrows,KDIM] @ W[KDIM,NC]
// blockDim.x = RPB * (NC/8). Each thread computes 1 row x 8 cols.
template <int KDIM, int NC, int RPB>
__global__ void k_gemm(const float* __restrict__ A, const float* __restrict__ W,
                       float* __restrict__ C, int nrows) {
    constexpr int TC = NC / 8;
    constexpr int APAD = KDIM + 4;   // bank-shift padding
    __shared__ float Ws[KDIM * NC];
    __shared__ float As[RPB * APAD];

    int tid = threadIdx.x;
    int nthr = blockDim.x;

    for (int i = tid; i < KDIM * NC / 4; i += nthr)
        ((float4*)Ws)[i] = ((const float4*)W)[i];

    int row0 = blockIdx.x * RPB;
    for (int i = tid; i < RPB * (KDIM / 4); i += nthr) {
        int r = i / (KDIM / 4);
        int kc = i % (KDIM / 4);
        int grow = row0 + r;
        float4 v = make_float4(0.f, 0.f, 0.f, 0.f);
        if (grow < nrows) v = ((const float4*)(A + (size_t)grow * KDIM))[kc];
        *(float4*)&As[r * APAD + kc * 4] = v;
    }
    __syncthreads();

    int r  = tid / TC;
    int c0 = (tid % TC) * 8;
    float acc[8];
#pragma unroll
    for (int j = 0; j < 8; j++) acc[j] = 0.f;

#pragma unroll 8
    for (int k = 0; k < KDIM; k++) {
        float a = As[r * APAD + k];
        float4 w0 = *(const float4*)&Ws[k * NC + c0];
        float4 w1 = *(const float4*)&Ws[k * NC + c0 + 4];
        acc[0] = fmaf(a, w0.x, acc[0]);
        acc[1] = fmaf(a, w0.y, acc[1]);
        acc[2] = fmaf(a, w0.z, acc[2]);
        acc[3] = fmaf(a, w0.w, acc[3]);
        acc[4] = fmaf(a, w1.x, acc[4]);
        acc[5] = fmaf(a, w1.y, acc[5]);
        acc[6] = fmaf(a, w1.z, acc[6]);
        acc[7] = fmaf(a, w1.w, acc[7]);
    }

    int grow = row0 + r;
    if (grow < nrows) {
        float4* op = (float4*)(C + (size_t)grow * NC + c0);
        op[0] = make_float4(acc[0], acc[1], acc[2], acc[3]);
        op[1] = make_float4(acc[4], acc[5], acc[6], acc[7]);
    }
}

// ---------------- CSR gather, 2-edge unrolled: out[row] = sum h[src]*norm
//                  + h[row]*dinv^2 + bias (+relu). thread = (node, float4-col).
template <int NC4, bool RELU>
__global__ void k_gather(const float* __restrict__ h, const float* __restrict__ bias,
                         float* __restrict__ out, int n) {
    int tid = blockIdx.x * blockDim.x + threadIdx.x;
    if (tid >= n * NC4) return;
    int row = tid / NC4;
    int c   = tid % NC4;

    const float4* h4 = (const float4*)h;
    float di = g_dinv[row];
    float s2 = di * di;

    // self loop
    float4 self = h4[(size_t)row * NC4 + c];
    float4 acc = make_float4(self.x * s2, self.y * s2, self.z * s2, self.w * s2);

    int beg = g_row_start[row];
    int end = g_row_start[row + 1];

    int j = beg;
    for (; j + 1 < end; j += 2) {            // unroll x2: independent load pairs -> 2x MLP
        int2 p0 = g_csr[j];
        int2 p1 = g_csr[j + 1];
        float4 v0 = h4[(size_t)p0.x * NC4 + c];
        float4 v1 = h4[(size_t)p1.x * NC4 + c];
        float nv0 = __int_as_float(p0.y);
        float nv1 = __int_as_float(p1.y);
        acc.x = fmaf(v0.x, nv0, acc.x);
        acc.y = fmaf(v0.y, nv0, acc.y);
        acc.z = fmaf(v0.z, nv0, acc.z);
        acc.w = fmaf(v0.w, nv0, acc.w);
        acc.x = fmaf(v1.x, nv1, acc.x);
        acc.y = fmaf(v1.y, nv1, acc.y);
        acc.z = fmaf(v1.z, nv1, acc.z);
        acc.w = fmaf(v1.w, nv1, acc.w);
    }
    if (j < end) {
        int2 p = g_csr[j];
        float nv = __int_as_float(p.y);
        float4 v = h4[(size_t)p.x * NC4 + c];
        acc.x = fmaf(v.x, nv, acc.x);
        acc.y = fmaf(v.y, nv, acc.y);
        acc.z = fmaf(v.z, nv, acc.z);
        acc.w = fmaf(v.w, nv, acc.w);
    }

    float4 b = ((const float4*)bias)[c];
    acc.x += b.x; acc.y += b.y; acc.z += b.z; acc.w += b.w;
    if (RELU) {
        acc.x = fmaxf(acc.x, 0.f); acc.y = fmaxf(acc.y, 0.f);
        acc.z = fmaxf(acc.z, 0.f); acc.w = fmaxf(acc.w, 0.f);
    }
    ((float4*)out)[(size_t)row * NC4 + c] = acc;
}

// ---------------- finalize: log_softmax in place, one warp per row ----------------
__global__ void k_finalize(float* __restrict__ out, int n) {
    int row = blockIdx.x * blockDim.y + threadIdx.y;
    if (row >= n) return;
    int lane = threadIdx.x;
    float* orow = out + (size_t)row * F2;

    float v0 = orow[lane];
    float v1 = 0.f;
    bool has2 = (lane < F2 - 32);
    if (has2) v1 = orow[lane + 32];

    float m = v0;
    if (has2) m = fmaxf(m, v1);
#pragma unroll
    for (int off = 16; off > 0; off >>= 1)
        m = fmaxf(m, __shfl_xor_sync(0xffffffffu, m, off));

    float s = expf(v0 - m);
    if (has2) s += expf(v1 - m);
#pragma unroll
    for (int off = 16; off > 0; off >>= 1)
        s += __shfl_xor_sync(0xffffffffu, s, off);

    float lse = m + logf(s);
    orow[lane] = v0 - lse;
    if (has2) orow[lane + 32] = v1 - lse;
}

// ---------------- host launcher ----------------
extern "C" void kernel_launch(void* const* d_in, const int* in_sizes, int n_in,
                              void* d_out, int out_size) {
    // Identify inputs by element count (all 7 distinct), robust to metadata order:
    //   x=N*128 (largest), edge_index=2E, edge_weight=E, W1=8192, W2=2560, b1=64, b2=40
    int order[16];
    for (int i = 0; i < n_in; i++) order[i] = i;
    for (int a = 0; a < n_in; a++)
        for (int bidx = a + 1; bidx < n_in; bidx++)
            if (in_sizes[order[bidx]] > in_sizes[order[a]]) {
                int t = order[a]; order[a] = order[bidx]; order[bidx] = t;
            }

    const float* x   = (const float*)d_in[order[0]];
    const int*   ei  = (const int*)  d_in[order[1]];   // int32 view; dtype sniffed on device
    const float* w   = (const float*)d_in[order[2]];
    const float* W1  = (const float*)d_in[order[3]];
    const float* W2  = (const float*)d_in[order[4]];
    const float* b1  = (const float*)d_in[order[5]];
    const float* b2  = (const float*)d_in[order[6]];
    float* out = (float*)d_out;

    int N = in_sizes[order[0]] / F0;   // 100000
    int E = in_sizes[order[2]];        // 1600000
    if (N > N_NODES) N = N_NODES;
    if (E > E_EDGES) E = E_EDGES;

    const int T = 256;
    int NB = (N + 1023) / 1024;

    // ---- init + dtype sniff + normalization + CSR build ----
    k_init<<<(N + T - 1) / T, T>>>(ei, N);                 // 0
    k_edge_prep<<<(E + T - 1) / T, T>>>(ei, w, E, N);      // 1
    k_scan1<<<NB, 1024>>>(N);                              // 2 (fused dinv)
    k_scan2<<<1, 128>>>(NB);                               // 3
    k_scan3<<<(N + T - 1) / T, T>>>(N, E);                 // 4
    k_fill<<<(E + T - 1) / T, T>>>(w, E);                  // 5

    // ---- layer 1 ----
    k_gemm<F0, F1, 16><<<(N + 15) / 16, 16 * (F1 / 8)>>>(x, W1, g_h1, N);            // 6
    k_gather<F1 / 4, true><<<(N * (F1 / 4) + T - 1) / T, T>>>(g_h1, b1, g_agg1, N);  // 7

    // ---- layer 2 ----
    k_gemm<F1, F2, 32><<<(N + 31) / 32, 32 * (F2 / 8)>>>(g_agg1, W2, g_h2, N);       // 8
    k_gather<F2 / 4, false><<<(N * (F2 / 4) + T - 1) / T, T>>>(g_h2, b2, out, N);    // 9

    // ---- log_softmax ----
    k_finalize<<<(N + 3) / 4, dim3(32, 4)>>>(out, N);                                // 10
}